// round 2
// baseline (speedup 1.0000x reference)
#include <cuda_runtime.h>

#define NB 4096     // anchors
#define ND 256      // dim
#define NL 4        // eps levels
#define NC 2048     // centroids per level
#define NN 100000   // labels per level

#define BM 32       // anchors per block
#define BN 128      // centroids per block tile
#define TK 32       // k-chunk
#define ASTR 36     // padded row stride (floats)
#define BSTR 36

__device__ float g_an[NB * ND];          // normalized anchors   (4 MB)
__device__ float g_cent[NL * NC * ND];   // normalized centroids (8 MB)
__device__ float g_mx[NB * NL];          // per (anchor, l) max over non-pos
__device__ float g_mn[NB * NL];          // per (anchor, l) min over pos

// ---------------------------------------------------------------------------
// Row L2 normalization: one warp per 256-wide row. which==0 -> g_an, 1 -> g_cent
// ---------------------------------------------------------------------------
__global__ void normalize_rows_kernel(const float* __restrict__ in, int rows, int which) {
    int row  = blockIdx.x * 8 + (threadIdx.x >> 5);
    int lane = threadIdx.x & 31;
    if (row >= rows) return;
    float* out = which ? g_cent : g_an;

    const float4* ip = reinterpret_cast<const float4*>(in) + (size_t)row * (ND / 4);
    float4 v0 = ip[lane];
    float4 v1 = ip[lane + 32];
    float ss = v0.x*v0.x + v0.y*v0.y + v0.z*v0.z + v0.w*v0.w
             + v1.x*v1.x + v1.y*v1.y + v1.z*v1.z + v1.w*v1.w;
    #pragma unroll
    for (int o = 16; o > 0; o >>= 1) ss += __shfl_xor_sync(0xffffffffu, ss, o);
    float scale = 1.0f / fmaxf(sqrtf(ss), 1e-12f);

    v0.x *= scale; v0.y *= scale; v0.z *= scale; v0.w *= scale;
    v1.x *= scale; v1.y *= scale; v1.z *= scale; v1.w *= scale;
    float4* op = reinterpret_cast<float4*>(out) + (size_t)row * (ND / 4);
    op[lane]      = v0;
    op[lane + 32] = v1;
}

// ---------------------------------------------------------------------------
// Fused GEMM + masked max/min reduction.
// Block: (anchor tile m0 of 32) x (eps level l). Loops over 16 tiles of 128
// centroids, K double-buffered in chunks of 32. Thread tile 4x8 (128 threads,
// 16x8 logical: tx in [0,16) -> 8 cols each (tx+16j), ty in [0,8) -> 4 rows).
// ---------------------------------------------------------------------------
__global__ void __launch_bounds__(128)
simred_kernel(const int* __restrict__ clab,
              const int* __restrict__ lpe,
              const int* __restrict__ lidx) {
    __shared__ float As[2][BM * ASTR];
    __shared__ float Bs[2][BN * BSTR];
    __shared__ int labA[BM];
    __shared__ int labC[BN];

    const int l   = blockIdx.y;
    const int m0  = blockIdx.x * BM;
    const int tid = threadIdx.x;
    const int tx  = tid & 15;
    const int ty  = tid >> 4;

    if (tid < BM) {
        int li = lidx[m0 + tid];
        labA[tid] = lpe[l * NN + li];
    }
    __syncthreads();

    int myLab[4];
    #pragma unroll
    for (int i = 0; i < 4; i++) myLab[i] = labA[ty * 4 + i];

    float mxv[4] = {-2.f, -2.f, -2.f, -2.f};
    float mnv[4] = { 2.f,  2.f,  2.f,  2.f};

    const float* anp = g_an  + (size_t)m0 * ND;
    const float* cp  = g_cent + (size_t)l * NC * ND;

    for (int n0 = 0; n0 < NC; n0 += BN) {
        labC[tid] = clab[l * NC + n0 + tid];   // BN == blockDim.x == 128

        // prologue: chunk 0 -> buffer 0
        #pragma unroll
        for (int it = 0; it < 2; it++) {               // A: 32x32 = 256 float4
            int q = tid + it * 128;
            int r = q >> 3, k4 = q & 7;
            float4 v = *reinterpret_cast<const float4*>(anp + (size_t)r * ND + k4 * 4);
            *reinterpret_cast<float4*>(&As[0][r * ASTR + k4 * 4]) = v;
        }
        #pragma unroll
        for (int it = 0; it < 8; it++) {               // B: 128x32 = 1024 float4
            int q = tid + it * 128;
            int r = q >> 3, k4 = q & 7;
            float4 v = *reinterpret_cast<const float4*>(cp + (size_t)(n0 + r) * ND + k4 * 4);
            *reinterpret_cast<float4*>(&Bs[0][r * BSTR + k4 * 4]) = v;
        }
        __syncthreads();

        int colLab[8];
        #pragma unroll
        for (int j = 0; j < 8; j++) colLab[j] = labC[tx + 16 * j];

        float acc[4][8];
        #pragma unroll
        for (int i = 0; i < 4; i++)
            #pragma unroll
            for (int j = 0; j < 8; j++) acc[i][j] = 0.f;

        #pragma unroll 1
        for (int kc = 0; kc < ND / TK; kc++) {
            const int cur = kc & 1, nxt = cur ^ 1;
            if (kc + 1 < ND / TK) {
                const int k0 = (kc + 1) * TK;
                #pragma unroll
                for (int it = 0; it < 2; it++) {
                    int q = tid + it * 128;
                    int r = q >> 3, k4 = q & 7;
                    float4 v = *reinterpret_cast<const float4*>(anp + (size_t)r * ND + k0 + k4 * 4);
                    *reinterpret_cast<float4*>(&As[nxt][r * ASTR + k4 * 4]) = v;
                }
                #pragma unroll
                for (int it = 0; it < 8; it++) {
                    int q = tid + it * 128;
                    int r = q >> 3, k4 = q & 7;
                    float4 v = *reinterpret_cast<const float4*>(cp + (size_t)(n0 + r) * ND + k0 + k4 * 4);
                    *reinterpret_cast<float4*>(&Bs[nxt][r * BSTR + k4 * 4]) = v;
                }
            }
            #pragma unroll
            for (int k4 = 0; k4 < TK / 4; k4++) {
                float4 a[4], b[8];
                #pragma unroll
                for (int i = 0; i < 4; i++)
                    a[i] = *reinterpret_cast<const float4*>(&As[cur][(ty * 4 + i) * ASTR + k4 * 4]);
                #pragma unroll
                for (int j = 0; j < 8; j++)
                    b[j] = *reinterpret_cast<const float4*>(&Bs[cur][(tx + 16 * j) * BSTR + k4 * 4]);
                #pragma unroll
                for (int i = 0; i < 4; i++)
                    #pragma unroll
                    for (int j = 0; j < 8; j++) {
                        acc[i][j] += a[i].x * b[j].x;
                        acc[i][j] += a[i].y * b[j].y;
                        acc[i][j] += a[i].z * b[j].z;
                        acc[i][j] += a[i].w * b[j].w;
                    }
            }
            __syncthreads();
        }

        // epilogue: fold tile into running masked max / min (registers only)
        #pragma unroll
        for (int i = 0; i < 4; i++) {
            #pragma unroll
            for (int j = 0; j < 8; j++) {
                float s = acc[i][j];
                bool isp = (myLab[i] >= 0) && (myLab[i] == colLab[j]);
                if (isp) mnv[i] = fminf(mnv[i], s);
                else     mxv[i] = fmaxf(mxv[i], s);
            }
        }
        __syncthreads();   // labC / smem safe to overwrite next tile
    }

    // reduce across the 16 column-threads (tx) sharing each anchor row
    #pragma unroll
    for (int i = 0; i < 4; i++) {
        float mx = mxv[i], mn = mnv[i];
        #pragma unroll
        for (int o = 8; o > 0; o >>= 1) {
            mx = fmaxf(mx, __shfl_xor_sync(0xffffffffu, mx, o));
            mn = fminf(mn, __shfl_xor_sync(0xffffffffu, mn, o));
        }
        if (tx == 0) {
            int b = m0 + ty * 4 + i;
            g_mx[b * NL + l] = mx;
            g_mn[b * NL + l] = mn;
        }
    }
}

// ---------------------------------------------------------------------------
// Final reduction: combine per-(anchor, l) partials -> scalar loss.
// has_neg is always true (<=4 positives among 8192 columns).
// ---------------------------------------------------------------------------
__global__ void finalize_kernel(float* __restrict__ out) {
    __shared__ float s_s[32], s_c[32];
    float sum = 0.f, cnt = 0.f;
    for (int b = threadIdx.x; b < NB; b += blockDim.x) {
        float mn = 2.f, mx = -2.f;
        #pragma unroll
        for (int l = 0; l < NL; l++) {
            mn = fminf(mn, g_mn[b * NL + l]);
            mx = fmaxf(mx, g_mx[b * NL + l]);
        }
        if (mn < 1.5f) {   // has_pos (any positive sim <= 1.0 < 1.5 < init 2.0)
            sum += fmaxf(mx - mn + 0.2f, 0.f);
            cnt += 1.f;
        }
    }
    #pragma unroll
    for (int o = 16; o > 0; o >>= 1) {
        sum += __shfl_xor_sync(0xffffffffu, sum, o);
        cnt += __shfl_xor_sync(0xffffffffu, cnt, o);
    }
    int w = threadIdx.x >> 5, lane = threadIdx.x & 31;
    if (lane == 0) { s_s[w] = sum; s_c[w] = cnt; }
    __syncthreads();
    if (w == 0) {
        sum = (lane < 32) ? s_s[lane] : 0.f;
        cnt = (lane < 32) ? s_c[lane] : 0.f;
        #pragma unroll
        for (int o = 16; o > 0; o >>= 1) {
            sum += __shfl_xor_sync(0xffffffffu, sum, o);
            cnt += __shfl_xor_sync(0xffffffffu, cnt, o);
        }
        if (lane == 0) out[0] = sum / fmaxf(cnt, 1.f);
    }
}

// ---------------------------------------------------------------------------
extern "C" void kernel_launch(void* const* d_in, const int* in_sizes, int n_in,
                              void* d_out, int out_size) {
    const float* anchors   = (const float*)d_in[0];   // [B, D]
    const float* centroids = (const float*)d_in[1];   // [L, C, D]
    const int*   clab      = (const int*)d_in[2];     // [L, C]
    const int*   lpe       = (const int*)d_in[3];     // [L, N]
    const int*   lidx      = (const int*)d_in[4];     // [B]

    normalize_rows_kernel<<<NB / 8, 256>>>(anchors, NB, 0);
    normalize_rows_kernel<<<(NL * NC) / 8, 256>>>(centroids, NL * NC, 1);

    dim3 grid(NB / BM, NL);
    simred_kernel<<<grid, 128>>>(clab, lpe, lidx);

    finalize_kernel<<<1, 1024>>>((float*)d_out);
}

// round 3
// speedup vs baseline: 1.0046x; 1.0046x over previous
#include <cuda_runtime.h>

#define NB 4096     // anchors
#define ND 256      // dim
#define NL 4        // eps levels
#define NC 2048     // centroids per level
#define NN 100000   // labels per level

#define BM 32       // anchors per block
#define BN 128      // centroids per block tile
#define TK 32       // k-chunk
#define ASTR 36     // padded row stride (floats)
#define BSTR 36

__device__ float g_an[NB * ND];          // normalized anchors   (4 MB)
__device__ float g_cent[NL * NC * ND];   // normalized centroids (8 MB)
__device__ float g_mx[NB * NL];          // per (anchor, l) max over non-pos
__device__ float g_mn[NB * NL];          // per (anchor, l) min over pos

// ---------------------------------------------------------------------------
// Row L2 normalization: one warp per 256-wide row. which==0 -> g_an, 1 -> g_cent
// ---------------------------------------------------------------------------
__global__ void normalize_rows_kernel(const float* __restrict__ in, int rows, int which) {
    int row  = blockIdx.x * 8 + (threadIdx.x >> 5);
    int lane = threadIdx.x & 31;
    if (row >= rows) return;
    float* out = which ? g_cent : g_an;

    const float4* ip = reinterpret_cast<const float4*>(in) + (size_t)row * (ND / 4);
    float4 v0 = ip[lane];
    float4 v1 = ip[lane + 32];
    float ss = v0.x*v0.x + v0.y*v0.y + v0.z*v0.z + v0.w*v0.w
             + v1.x*v1.x + v1.y*v1.y + v1.z*v1.z + v1.w*v1.w;
    #pragma unroll
    for (int o = 16; o > 0; o >>= 1) ss += __shfl_xor_sync(0xffffffffu, ss, o);
    float scale = 1.0f / fmaxf(sqrtf(ss), 1e-12f);

    v0.x *= scale; v0.y *= scale; v0.z *= scale; v0.w *= scale;
    v1.x *= scale; v1.y *= scale; v1.z *= scale; v1.w *= scale;
    float4* op = reinterpret_cast<float4*>(out) + (size_t)row * (ND / 4);
    op[lane]      = v0;
    op[lane + 32] = v1;
}

// ---------------------------------------------------------------------------
// Fused GEMM + masked max/min reduction.
// Block: (anchor tile m0 of 32) x (eps level l). Loops over 16 tiles of 128
// centroids, K double-buffered in chunks of 32. Thread tile 4x8 (128 threads,
// 16x8 logical: tx in [0,16) -> 8 cols each (tx+16j), ty in [0,8) -> 4 rows).
// ---------------------------------------------------------------------------
__global__ void __launch_bounds__(128)
simred_kernel(const int* __restrict__ clab,
              const int* __restrict__ lpe,
              const int* __restrict__ lidx) {
    __shared__ float As[2][BM * ASTR];
    __shared__ float Bs[2][BN * BSTR];
    __shared__ int labA[BM];
    __shared__ int labC[BN];

    const int l   = blockIdx.y;
    const int m0  = blockIdx.x * BM;
    const int tid = threadIdx.x;
    const int tx  = tid & 15;
    const int ty  = tid >> 4;

    if (tid < BM) {
        int li = lidx[m0 + tid];
        labA[tid] = lpe[l * NN + li];
    }
    __syncthreads();

    int myLab[4];
    #pragma unroll
    for (int i = 0; i < 4; i++) myLab[i] = labA[ty * 4 + i];

    float mxv[4] = {-2.f, -2.f, -2.f, -2.f};
    float mnv[4] = { 2.f,  2.f,  2.f,  2.f};

    const float* anp = g_an  + (size_t)m0 * ND;
    const float* cp  = g_cent + (size_t)l * NC * ND;

    for (int n0 = 0; n0 < NC; n0 += BN) {
        labC[tid] = clab[l * NC + n0 + tid];   // BN == blockDim.x == 128

        // prologue: chunk 0 -> buffer 0
        #pragma unroll
        for (int it = 0; it < 2; it++) {               // A: 32x32 = 256 float4
            int q = tid + it * 128;
            int r = q >> 3, k4 = q & 7;
            float4 v = *reinterpret_cast<const float4*>(anp + (size_t)r * ND + k4 * 4);
            *reinterpret_cast<float4*>(&As[0][r * ASTR + k4 * 4]) = v;
        }
        #pragma unroll
        for (int it = 0; it < 8; it++) {               // B: 128x32 = 1024 float4
            int q = tid + it * 128;
            int r = q >> 3, k4 = q & 7;
            float4 v = *reinterpret_cast<const float4*>(cp + (size_t)(n0 + r) * ND + k4 * 4);
            *reinterpret_cast<float4*>(&Bs[0][r * BSTR + k4 * 4]) = v;
        }
        __syncthreads();

        int colLab[8];
        #pragma unroll
        for (int j = 0; j < 8; j++) colLab[j] = labC[tx + 16 * j];

        float acc[4][8];
        #pragma unroll
        for (int i = 0; i < 4; i++)
            #pragma unroll
            for (int j = 0; j < 8; j++) acc[i][j] = 0.f;

        #pragma unroll 1
        for (int kc = 0; kc < ND / TK; kc++) {
            const int cur = kc & 1, nxt = cur ^ 1;
            if (kc + 1 < ND / TK) {
                const int k0 = (kc + 1) * TK;
                #pragma unroll
                for (int it = 0; it < 2; it++) {
                    int q = tid + it * 128;
                    int r = q >> 3, k4 = q & 7;
                    float4 v = *reinterpret_cast<const float4*>(anp + (size_t)r * ND + k0 + k4 * 4);
                    *reinterpret_cast<float4*>(&As[nxt][r * ASTR + k4 * 4]) = v;
                }
                #pragma unroll
                for (int it = 0; it < 8; it++) {
                    int q = tid + it * 128;
                    int r = q >> 3, k4 = q & 7;
                    float4 v = *reinterpret_cast<const float4*>(cp + (size_t)(n0 + r) * ND + k0 + k4 * 4);
                    *reinterpret_cast<float4*>(&Bs[nxt][r * BSTR + k4 * 4]) = v;
                }
            }
            #pragma unroll
            for (int k4 = 0; k4 < TK / 4; k4++) {
                float4 a[4], b[8];
                #pragma unroll
                for (int i = 0; i < 4; i++)
                    a[i] = *reinterpret_cast<const float4*>(&As[cur][(ty * 4 + i) * ASTR + k4 * 4]);
                #pragma unroll
                for (int j = 0; j < 8; j++)
                    b[j] = *reinterpret_cast<const float4*>(&Bs[cur][(tx + 16 * j) * BSTR + k4 * 4]);
                #pragma unroll
                for (int i = 0; i < 4; i++)
                    #pragma unroll
                    for (int j = 0; j < 8; j++) {
                        acc[i][j] += a[i].x * b[j].x;
                        acc[i][j] += a[i].y * b[j].y;
                        acc[i][j] += a[i].z * b[j].z;
                        acc[i][j] += a[i].w * b[j].w;
                    }
            }
            __syncthreads();
        }

        // epilogue: fold tile into running masked max / min (registers only)
        #pragma unroll
        for (int i = 0; i < 4; i++) {
            #pragma unroll
            for (int j = 0; j < 8; j++) {
                float s = acc[i][j];
                bool isp = (myLab[i] >= 0) && (myLab[i] == colLab[j]);
                if (isp) mnv[i] = fminf(mnv[i], s);
                else     mxv[i] = fmaxf(mxv[i], s);
            }
        }
        __syncthreads();   // labC / smem safe to overwrite next tile
    }

    // reduce across the 16 column-threads (tx) sharing each anchor row
    #pragma unroll
    for (int i = 0; i < 4; i++) {
        float mx = mxv[i], mn = mnv[i];
        #pragma unroll
        for (int o = 8; o > 0; o >>= 1) {
            mx = fmaxf(mx, __shfl_xor_sync(0xffffffffu, mx, o));
            mn = fminf(mn, __shfl_xor_sync(0xffffffffu, mn, o));
        }
        if (tx == 0) {
            int b = m0 + ty * 4 + i;
            g_mx[b * NL + l] = mx;
            g_mn[b * NL + l] = mn;
        }
    }
}

// ---------------------------------------------------------------------------
// Final reduction: combine per-(anchor, l) partials -> scalar loss.
// has_neg is always true (<=4 positives among 8192 columns).
// ---------------------------------------------------------------------------
__global__ void finalize_kernel(float* __restrict__ out) {
    __shared__ float s_s[32], s_c[32];
    float sum = 0.f, cnt = 0.f;
    for (int b = threadIdx.x; b < NB; b += blockDim.x) {
        float mn = 2.f, mx = -2.f;
        #pragma unroll
        for (int l = 0; l < NL; l++) {
            mn = fminf(mn, g_mn[b * NL + l]);
            mx = fmaxf(mx, g_mx[b * NL + l]);
        }
        if (mn < 1.5f) {   // has_pos (any positive sim <= 1.0 < 1.5 < init 2.0)
            sum += fmaxf(mx - mn + 0.2f, 0.f);
            cnt += 1.f;
        }
    }
    #pragma unroll
    for (int o = 16; o > 0; o >>= 1) {
        sum += __shfl_xor_sync(0xffffffffu, sum, o);
        cnt += __shfl_xor_sync(0xffffffffu, cnt, o);
    }
    int w = threadIdx.x >> 5, lane = threadIdx.x & 31;
    if (lane == 0) { s_s[w] = sum; s_c[w] = cnt; }
    __syncthreads();
    if (w == 0) {
        sum = (lane < 32) ? s_s[lane] : 0.f;
        cnt = (lane < 32) ? s_c[lane] : 0.f;
        #pragma unroll
        for (int o = 16; o > 0; o >>= 1) {
            sum += __shfl_xor_sync(0xffffffffu, sum, o);
            cnt += __shfl_xor_sync(0xffffffffu, cnt, o);
        }
        if (lane == 0) out[0] = sum / fmaxf(cnt, 1.f);
    }
}

// ---------------------------------------------------------------------------
extern "C" void kernel_launch(void* const* d_in, const int* in_sizes, int n_in,
                              void* d_out, int out_size) {
    const float* anchors   = (const float*)d_in[0];   // [B, D]
    const float* centroids = (const float*)d_in[1];   // [L, C, D]
    const int*   clab      = (const int*)d_in[2];     // [L, C]
    const int*   lpe       = (const int*)d_in[3];     // [L, N]
    const int*   lidx      = (const int*)d_in[4];     // [B]

    normalize_rows_kernel<<<NB / 8, 256>>>(anchors, NB, 0);
    normalize_rows_kernel<<<(NL * NC) / 8, 256>>>(centroids, NL * NC, 1);

    dim3 grid(NB / BM, NL);
    simred_kernel<<<grid, 128>>>(clab, lpe, lidx);

    finalize_kernel<<<1, 1024>>>((float*)d_out);
}

// round 5
// speedup vs baseline: 4.0794x; 4.0606x over previous
#include <cuda_runtime.h>
#include <cuda_bf16.h>
#include <cstdint>

#define NB 4096     // anchors
#define ND 256      // dim
#define NL 4        // eps levels
#define NC 2048     // centroids per level
#define NN 100000   // labels per level
#define NFLAT (NL*NC)   // 8192 flat centroids
#define NTILES 64       // 8192 / 128 N-tiles

// ---------------- device scratch (allocation-free) ----------------
__device__ __nv_bfloat16 g_an_hi[NB * ND];
__device__ __nv_bfloat16 g_an_lo[NB * ND];
__device__ __nv_bfloat16 g_c_hi[NFLAT * ND];
__device__ __nv_bfloat16 g_c_lo[NFLAT * ND];
__device__ float g_pmx[NTILES * NB];   // [ntile][row] max over non-pos
__device__ float g_pmn[NTILES * NB];   // [ntile][row] min over pos
__device__ float g_bsum[32];
__device__ float g_bcnt[32];

__device__ __forceinline__ uint32_t smem_u32(const void* p) {
    uint32_t a;
    asm("{ .reg .u64 t; cvta.to.shared.u64 t, %1; cvt.u32.u64 %0, t; }" : "=r"(a) : "l"(p));
    return a;
}

// ldmatrix x4 (b16, non-transposed)
#define LDSM4(f, addr) \
    asm volatile("ldmatrix.sync.aligned.m8n8.x4.shared.b16 {%0,%1,%2,%3}, [%4];" \
        : "=r"((f)[0]), "=r"((f)[1]), "=r"((f)[2]), "=r"((f)[3]) : "r"(addr))

// mma m16n8k16 bf16 -> fp32
#define MMA16816(d, a, b0, b1) \
    asm volatile("mma.sync.aligned.m16n8k16.row.col.f32.bf16.bf16.f32 " \
        "{%0,%1,%2,%3},{%4,%5,%6,%7},{%8,%9},{%0,%1,%2,%3};" \
        : "+f"((d)[0]), "+f"((d)[1]), "+f"((d)[2]), "+f"((d)[3]) \
        : "r"((a)[0]), "r"((a)[1]), "r"((a)[2]), "r"((a)[3]), "r"(b0), "r"(b1))

// ---------------------------------------------------------------------------
// Normalize + bf16 hi/lo split. One warp per 256-wide row.
// ---------------------------------------------------------------------------
__global__ void prep_kernel(const float* __restrict__ in, int rows, int which) {
    int row  = blockIdx.x * 8 + (threadIdx.x >> 5);
    int lane = threadIdx.x & 31;
    if (row >= rows) return;

    const float4* ip = reinterpret_cast<const float4*>(in) + (size_t)row * (ND / 4);
    float4 v0 = ip[lane];
    float4 v1 = ip[lane + 32];
    float ss = v0.x*v0.x + v0.y*v0.y + v0.z*v0.z + v0.w*v0.w
             + v1.x*v1.x + v1.y*v1.y + v1.z*v1.z + v1.w*v1.w;
    #pragma unroll
    for (int o = 16; o > 0; o >>= 1) ss += __shfl_xor_sync(0xffffffffu, ss, o);
    float scale = 1.0f / fmaxf(sqrtf(ss), 1e-12f);

    __nv_bfloat16* oh = which ? g_c_hi : g_an_hi;
    __nv_bfloat16* ol = which ? g_c_lo : g_an_lo;
    size_t base = (size_t)row * ND;

    float v[8] = {v0.x, v0.y, v0.z, v0.w, v1.x, v1.y, v1.z, v1.w};
    #pragma unroll
    for (int j = 0; j < 8; j++) {
        float x = v[j] * scale;
        size_t idx = base + (j < 4 ? lane * 4 + j : 128 + lane * 4 + (j - 4));
        __nv_bfloat16 h = __float2bfloat16(x);
        oh[idx] = h;
        ol[idx] = __float2bfloat16(x - __bfloat162float(h));
    }
}

// ---------------------------------------------------------------------------
// HMMA (mma.sync bf16) 3-split GEMM + masked max/min epilogue.
// CTA tile 128x128, 8 warps in 2(M) x 4(N), warp tile 64x32.
// K = 256 in 4 chunks of 64 staged in SMEM (stride 72 bf16, conflict-free).
// ---------------------------------------------------------------------------
#define LDS 72
#define AH_OFF 0
#define AL_OFF (128*LDS)
#define BH_OFF (2*128*LDS)
#define BL_OFF (3*128*LDS)
#define TILE_BYTES (4*128*LDS*2)          // 73728
#define SMEM_TOTAL (TILE_BYTES + 1024 + 4096)

__global__ void __launch_bounds__(256, 2)
gemm_kernel(const int* __restrict__ clab,
            const int* __restrict__ lpe,
            const int* __restrict__ lidx) {
    extern __shared__ char smem[];
    __nv_bfloat16* ts = reinterpret_cast<__nv_bfloat16*>(smem);
    int*   labA  = reinterpret_cast<int*>(smem + TILE_BYTES);         // 128
    int*   labC  = labA + 128;                                        // 128
    float* redmx = reinterpret_cast<float*>(labC + 128);              // 4*128
    float* redmn = redmx + 512;                                       // 4*128

    const int tid    = threadIdx.x;
    const int lane   = tid & 31;
    const int wid    = tid >> 5;
    const int warp_m = wid >> 2;          // 0..1
    const int warp_n = wid & 3;           // 0..3
    const int m0     = blockIdx.x * 128;
    const int ntile  = blockIdx.y;
    const int n0     = ntile * 128;
    const int l      = n0 >> 11;          // tile fully within one eps level

    if (tid < 128) labA[tid] = lpe[l * NN + lidx[m0 + tid]];
    else           labC[tid - 128] = clab[n0 + tid - 128];

    float acc[4][4][4];
    #pragma unroll
    for (int mt = 0; mt < 4; mt++)
        #pragma unroll
        for (int nt = 0; nt < 4; nt++)
            #pragma unroll
            for (int e = 0; e < 4; e++) acc[mt][nt][e] = 0.f;

    const __nv_bfloat16* gAh = g_an_hi + (size_t)m0 * ND;
    const __nv_bfloat16* gAl = g_an_lo + (size_t)m0 * ND;
    const __nv_bfloat16* gBh = g_c_hi  + (size_t)n0 * ND;
    const __nv_bfloat16* gBl = g_c_lo  + (size_t)n0 * ND;

    const uint32_t sb = smem_u32(ts);
    // ldmatrix lane addressing (A: m16 x k16; B: n16 x k16, both k-contiguous)
    const int arow  = lane & 15;
    const int acol8 = (lane >> 4) * 8;
    const int brow  = (lane & 7) + ((lane >> 4) << 3);
    const int bcol8 = ((lane >> 3) & 1) * 8;

    for (int kc = 0; kc < 4; kc++) {
        __syncthreads();
        #pragma unroll
        for (int it = 0; it < 4; it++) {
            int q = tid + it * 256;
            int r = q >> 3, k8 = q & 7;
            int    so = r * LDS + k8 * 8;
            size_t go = (size_t)r * ND + kc * 64 + k8 * 8;
            *reinterpret_cast<float4*>(ts + AH_OFF + so) = *reinterpret_cast<const float4*>(gAh + go);
            *reinterpret_cast<float4*>(ts + AL_OFF + so) = *reinterpret_cast<const float4*>(gAl + go);
            *reinterpret_cast<float4*>(ts + BH_OFF + so) = *reinterpret_cast<const float4*>(gBh + go);
            *reinterpret_cast<float4*>(ts + BL_OFF + so) = *reinterpret_cast<const float4*>(gBl + go);
        }
        __syncthreads();

        #pragma unroll
        for (int ks = 0; ks < 4; ks++) {
            const int k0 = ks * 16;
            uint32_t af[4][4], bh[2][4], bx[2][4];

            #pragma unroll
            for (int bt = 0; bt < 2; bt++) {
                uint32_t addr = sb + 2u * (BH_OFF + (warp_n * 32 + bt * 16 + brow) * LDS + k0 + bcol8);
                LDSM4(bh[bt], addr);
            }
            #pragma unroll
            for (int mt = 0; mt < 4; mt++) {
                uint32_t addr = sb + 2u * (AH_OFF + (warp_m * 64 + mt * 16 + arow) * LDS + k0 + acol8);
                LDSM4(af[mt], addr);
            }
            // pass 1: hi * hi
            #pragma unroll
            for (int mt = 0; mt < 4; mt++)
                #pragma unroll
                for (int bt = 0; bt < 2; bt++)
                    #pragma unroll
                    for (int j = 0; j < 2; j++)
                        MMA16816(acc[mt][bt * 2 + j], af[mt], bh[bt][j * 2], bh[bt][j * 2 + 1]);

            // pass 2: hi * lo
            #pragma unroll
            for (int bt = 0; bt < 2; bt++) {
                uint32_t addr = sb + 2u * (BL_OFF + (warp_n * 32 + bt * 16 + brow) * LDS + k0 + bcol8);
                LDSM4(bx[bt], addr);
            }
            #pragma unroll
            for (int mt = 0; mt < 4; mt++)
                #pragma unroll
                for (int bt = 0; bt < 2; bt++)
                    #pragma unroll
                    for (int j = 0; j < 2; j++)
                        MMA16816(acc[mt][bt * 2 + j], af[mt], bx[bt][j * 2], bx[bt][j * 2 + 1]);

            // pass 3: lo * hi (reuse af regs for A_lo)
            #pragma unroll
            for (int mt = 0; mt < 4; mt++) {
                uint32_t addr = sb + 2u * (AL_OFF + (warp_m * 64 + mt * 16 + arow) * LDS + k0 + acol8);
                LDSM4(af[mt], addr);
            }
            #pragma unroll
            for (int mt = 0; mt < 4; mt++)
                #pragma unroll
                for (int bt = 0; bt < 2; bt++)
                    #pragma unroll
                    for (int j = 0; j < 2; j++)
                        MMA16816(acc[mt][bt * 2 + j], af[mt], bh[bt][j * 2], bh[bt][j * 2 + 1]);
        }
    }

    // ---- epilogue: masked max/min from register fragments ----
    // fragment: d[h*2+cp] at row = lane/4 + h*8, col = (lane&3)*2 + cp
    int collab[4][2], rowlab[4][2];
    #pragma unroll
    for (int nt = 0; nt < 4; nt++) {
        collab[nt][0] = labC[warp_n * 32 + nt * 8 + (lane & 3) * 2];
        collab[nt][1] = labC[warp_n * 32 + nt * 8 + (lane & 3) * 2 + 1];
    }
    #pragma unroll
    for (int mt = 0; mt < 4; mt++) {
        rowlab[mt][0] = labA[warp_m * 64 + mt * 16 + (lane >> 2)];
        rowlab[mt][1] = labA[warp_m * 64 + mt * 16 + (lane >> 2) + 8];
    }

    #pragma unroll
    for (int mt = 0; mt < 4; mt++) {
        #pragma unroll
        for (int h = 0; h < 2; h++) {
            int rl = rowlab[mt][h];
            float mx = -2.f, mn = 2.f;
            #pragma unroll
            for (int nt = 0; nt < 4; nt++) {
                #pragma unroll
                for (int cp = 0; cp < 2; cp++) {
                    float s = acc[mt][nt][h * 2 + cp];
                    bool isp = (rl >= 0) && (rl == collab[nt][cp]);
                    if (isp) mn = fminf(mn, s);
                    else     mx = fmaxf(mx, s);
                }
            }
            #pragma unroll
            for (int o = 1; o <= 2; o <<= 1) {
                mx = fmaxf(mx, __shfl_xor_sync(0xffffffffu, mx, o));
                mn = fminf(mn, __shfl_xor_sync(0xffffffffu, mn, o));
            }
            if ((lane & 3) == 0) {
                int rloc = warp_m * 64 + mt * 16 + (lane >> 2) + h * 8;
                redmx[warp_n * 128 + rloc] = mx;
                redmn[warp_n * 128 + rloc] = mn;
            }
        }
    }
    __syncthreads();

    if (tid < 128) {
        float mx = redmx[tid], mn = redmn[tid];
        #pragma unroll
        for (int w = 1; w < 4; w++) {
            mx = fmaxf(mx, redmx[w * 128 + tid]);
            mn = fminf(mn, redmn[w * 128 + tid]);
        }
        g_pmx[(size_t)ntile * NB + m0 + tid] = mx;
        g_pmn[(size_t)ntile * NB + m0 + tid] = mn;
    }
}

// ---------------------------------------------------------------------------
// Reduce per-tile partials across 64 N-tiles -> per-block partial loss sums.
// ---------------------------------------------------------------------------
__global__ void reduce_kernel() {
    int row = blockIdx.x * 128 + threadIdx.x;   // 32 blocks x 128 = 4096 rows
    int wid = threadIdx.x >> 5, lane = threadIdx.x & 31;

    float mn = 2.f, mx = -2.f;
    #pragma unroll 4
    for (int t = 0; t < NTILES; t++) {
        mn = fminf(mn, g_pmn[(size_t)t * NB + row]);
        mx = fmaxf(mx, g_pmx[(size_t)t * NB + row]);
    }
    float per = 0.f, c = 0.f;
    if (mn < 1.5f) {                             // has_pos; has_neg always true
        per = fmaxf(mx - mn + 0.2f, 0.f);
        c = 1.f;
    }
    #pragma unroll
    for (int o = 16; o > 0; o >>= 1) {
        per += __shfl_xor_sync(0xffffffffu, per, o);
        c   += __shfl_xor_sync(0xffffffffu, c, o);
    }
    __shared__ float ss[4], sc[4];
    if (lane == 0) { ss[wid] = per; sc[wid] = c; }
    __syncthreads();
    if (threadIdx.x == 0) {
        g_bsum[blockIdx.x] = ss[0] + ss[1] + ss[2] + ss[3];
        g_bcnt[blockIdx.x] = sc[0] + sc[1] + sc[2] + sc[3];
    }
}

__global__ void final_kernel(float* __restrict__ out) {
    int lane = threadIdx.x;
    float s = g_bsum[lane], c = g_bcnt[lane];
    #pragma unroll
    for (int o = 16; o > 0; o >>= 1) {
        s += __shfl_xor_sync(0xffffffffu, s, o);
        c += __shfl_xor_sync(0xffffffffu, c, o);
    }
    if (lane == 0) out[0] = s / fmaxf(c, 1.f);
}

// ---------------------------------------------------------------------------
extern "C" void kernel_launch(void* const* d_in, const int* in_sizes, int n_in,
                              void* d_out, int out_size) {
    const float* anchors   = (const float*)d_in[0];   // [B, D]
    const float* centroids = (const float*)d_in[1];   // [L, C, D]
    const int*   clab      = (const int*)d_in[2];     // [L, C]
    const int*   lpe       = (const int*)d_in[3];     // [L, N]
    const int*   lidx      = (const int*)d_in[4];     // [B]

    static int configured = 0;
    if (!configured) {
        cudaFuncSetAttribute(gemm_kernel, cudaFuncAttributeMaxDynamicSharedMemorySize, SMEM_TOTAL);
        configured = 1;
    }

    prep_kernel<<<NB / 8, 256>>>(anchors, NB, 0);
    prep_kernel<<<NFLAT / 8, 256>>>(centroids, NFLAT, 1);

    dim3 grid(NB / 128, NTILES);
    gemm_kernel<<<grid, 256, SMEM_TOTAL>>>(clab, lpe, lidx);

    reduce_kernel<<<32, 128>>>();
    final_kernel<<<1, 32>>>((float*)d_out);
}